// round 9
// baseline (speedup 1.0000x reference)
#include <cuda_runtime.h>

// ---------------------------------------------------------------------------
// MambaBlock: seq(B,L,d); per layer: LN -> u = n@Wi^T+bi -> ub = dt*u@Bp^T
// -> chunked linear scan h = Abar h + ub -> y = hs@Cp^T + u*Dp
// -> seq += y@Wo^T + bo.   All fp32.
// ---------------------------------------------------------------------------

#define B_N    8
#define L_SEQ  1024
#define D_DIM  1024
#define S_DIM  128
#define DEPTH  4
#define T_CHUNK 32
#define KC_CHUNKS 32
#define DT_F   0.001f

// ------------------------- device scratch (allowed) ------------------------
__device__ float g_seq[(size_t)B_N * L_SEQ * D_DIM];   // residual stream
__device__ float g_t1 [(size_t)B_N * L_SEQ * D_DIM];   // n (then reused as y)
__device__ float g_u  [(size_t)B_N * L_SEQ * D_DIM];   // u
__device__ float g_ub [(size_t)B_N * L_SEQ * S_DIM];   // ub (b,l,s)
__device__ float g_hs [(size_t)B_N * L_SEQ * S_DIM];   // hs (b,l,s)
__device__ float g_Abar[DEPTH * S_DIM * S_DIM];
__device__ float g_p0  [DEPTH * S_DIM * S_DIM];
__device__ float g_p1  [DEPTH * S_DIM * S_DIM];
__device__ float g_lf  [KC_CHUNKS * B_N * S_DIM];      // local chunk finals
__device__ float g_ci  [KC_CHUNKS * B_N * S_DIM];      // carry-in per chunk

// ------------------------------ transpose ---------------------------------
// out[b][j][i] = in[b][i][j], 1024x1024 per batch.  grid(32,32,8) block(32,8)
__global__ void __launch_bounds__(256)
transpose_kernel(const float* __restrict__ in, float* __restrict__ out)
{
    __shared__ float tile[32][33];
    const int b  = blockIdx.z;
    const int i0 = blockIdx.y * 32, j0 = blockIdx.x * 32;
    const int tx = threadIdx.x, ty = threadIdx.y;
    const float* src = in  + (size_t)b * 1048576;
    float*       dst = out + (size_t)b * 1048576;
#pragma unroll
    for (int r = 0; r < 32; r += 8)
        tile[ty + r][tx] = src[(size_t)(i0 + ty + r) * 1024 + j0 + tx];
    __syncthreads();
#pragma unroll
    for (int r = 0; r < 32; r += 8)
        dst[(size_t)(j0 + ty + r) * 1024 + i0 + tx] = tile[tx][ty + r];
}

// ------------------------------ layernorm ---------------------------------
// one block per row of 1024, 256 threads, 1 float4 each
__global__ void __launch_bounds__(256)
layernorm_kernel(const float* __restrict__ x, const float* __restrict__ gamma,
                 const float* __restrict__ beta, float* __restrict__ out)
{
    const int row = blockIdx.x, tid = threadIdx.x;
    const float4 v = ((const float4*)(x + (size_t)row * 1024))[tid];
    float s  = v.x + v.y + v.z + v.w;
    float ss = v.x*v.x + v.y*v.y + v.z*v.z + v.w*v.w;
#pragma unroll
    for (int o = 16; o; o >>= 1) {
        s  += __shfl_xor_sync(0xffffffffu, s,  o);
        ss += __shfl_xor_sync(0xffffffffu, ss, o);
    }
    __shared__ float sh_s[8], sh_ss[8];
    if ((tid & 31) == 0) { sh_s[tid >> 5] = s; sh_ss[tid >> 5] = ss; }
    __syncthreads();
    if (tid < 32) {
        float a = (tid < 8) ? sh_s[tid]  : 0.f;
        float c = (tid < 8) ? sh_ss[tid] : 0.f;
#pragma unroll
        for (int o = 4; o; o >>= 1) {
            a += __shfl_xor_sync(0xffffffffu, a, o);
            c += __shfl_xor_sync(0xffffffffu, c, o);
        }
        if (tid == 0) { sh_s[0] = a; sh_ss[0] = c; }
    }
    __syncthreads();
    const float mean = sh_s[0] * (1.f / 1024.f);
    const float var  = sh_ss[0] * (1.f / 1024.f) - mean * mean;
    const float rstd = rsqrtf(var + 1e-5f);
    const float4 g = ((const float4*)gamma)[tid];
    const float4 bb = ((const float4*)beta)[tid];
    float4 o;
    o.x = (v.x - mean) * rstd * g.x + bb.x;
    o.y = (v.y - mean) * rstd * g.y + bb.y;
    o.z = (v.z - mean) * rstd * g.z + bb.z;
    o.w = (v.w - mean) * rstd * g.w + bb.w;
    ((float4*)(out + (size_t)row * 1024))[tid] = o;
}

// ------------------------------- GEMM --------------------------------------
// C(MxN) = alpha * A(MxK) @ op(B) (+ epilogue), BT: B is (N,K) -> A@B^T,
// else B is (K,N). EPI: 0 none | 1 +bias[n] | 2 +U[m,n]*Dp[n] | 3 +bias[n]+Cin[m,n]
// 256 threads; BM*BK == BN*BK == 1024 floats (1 float4/thread/tile).
template<int BM,int BN,int BK,int TM,int TN,int EPI,bool BT>
__global__ void __launch_bounds__(256)
gemm_kernel(const float* __restrict__ A, const float* __restrict__ B,
            float* __restrict__ C, int M, int N, int K, float alpha,
            const float* __restrict__ bias, const float* __restrict__ U,
            const float* __restrict__ Dp, const float* __restrict__ Cin,
            size_t sA, size_t sB, size_t sC)
{
    static_assert(BM * BK == 1024 && BN * BK == 1024, "tile load sizing");
    static_assert(BM == BN, "BT loader assumes BM==BN");
    __shared__ float As[BK][BM];
    __shared__ float Bs[BK][BN];
    A += (size_t)blockIdx.z * sA;
    B += (size_t)blockIdx.z * sB;
    C += (size_t)blockIdx.z * sC;

    const int tid = threadIdx.x;
    const int m0 = blockIdx.y * BM;
    const int n0 = blockIdx.x * BN;
    const int tx = tid & 15;
    const int ty = tid >> 4;

    const int af4  = BK / 4;
    const int aRow = tid / af4;            // 0..BM-1
    const int aCol = (tid % af4) * 4;      // 0..BK-4
    const int bf4n  = BN / 4;
    const int bRowN = tid / bf4n;          // 0..BK-1
    const int bColN = (tid % bf4n) * 4;

    const float* aPtr = A + (size_t)(m0 + aRow) * K + aCol;
    const float* bPtr = BT ? (B + (size_t)(n0 + aRow) * K + aCol)
                           : (B + (size_t)bRowN * N + n0 + bColN);
    float4 aReg = *(const float4*)aPtr;
    float4 bReg = *(const float4*)bPtr;

    float acc[TM][TN];
#pragma unroll
    for (int i = 0; i < TM; i++)
#pragma unroll
        for (int j = 0; j < TN; j++) acc[i][j] = 0.f;

    const int KT = K / BK;
    for (int kt = 0; kt < KT; ++kt) {
        __syncthreads();
        As[aCol + 0][aRow] = aReg.x; As[aCol + 1][aRow] = aReg.y;
        As[aCol + 2][aRow] = aReg.z; As[aCol + 3][aRow] = aReg.w;
        if (BT) {
            Bs[aCol + 0][aRow] = bReg.x; Bs[aCol + 1][aRow] = bReg.y;
            Bs[aCol + 2][aRow] = bReg.z; Bs[aCol + 3][aRow] = bReg.w;
        } else {
            *(float4*)&Bs[bRowN][bColN] = bReg;
        }
        __syncthreads();
        if (kt + 1 < KT) {
            aPtr += BK;
            aReg = *(const float4*)aPtr;
            if (BT) bPtr += BK; else bPtr += (size_t)BK * N;
            bReg = *(const float4*)bPtr;
        }
#pragma unroll
        for (int k = 0; k < BK; k++) {
            float ar[TM], br[TN];
            float4 q;
            q = *(const float4*)&As[k][ty * 4];
            ar[0] = q.x; ar[1] = q.y; ar[2] = q.z; ar[3] = q.w;
            if (TM == 8) {
                q = *(const float4*)&As[k][BM / 2 + ty * 4];
                ar[4] = q.x; ar[5] = q.y; ar[6] = q.z; ar[7] = q.w;
            }
            q = *(const float4*)&Bs[k][tx * 4];
            br[0] = q.x; br[1] = q.y; br[2] = q.z; br[3] = q.w;
            if (TN == 8) {
                q = *(const float4*)&Bs[k][BN / 2 + tx * 4];
                br[4] = q.x; br[5] = q.y; br[6] = q.z; br[7] = q.w;
            }
#pragma unroll
            for (int i = 0; i < TM; i++)
#pragma unroll
                for (int j = 0; j < TN; j++)
                    acc[i][j] = fmaf(ar[i], br[j], acc[i][j]);
        }
    }

#pragma unroll
    for (int i = 0; i < TM; i++) {
        const int mi = m0 + ((TM == 8) ? ((i & 3) + ty * 4 + (i >> 2) * (BM / 2))
                                       : (ty * 4 + i));
#pragma unroll
        for (int j = 0; j < TN; j++) {
            const int nj = n0 + ((TN == 8) ? ((j & 3) + tx * 4 + (j >> 2) * (BN / 2))
                                           : (tx * 4 + j));
            float v = alpha * acc[i][j];
            if (EPI == 1)      v += bias[nj];
            else if (EPI == 2) v += U[(size_t)mi * N + nj] * Dp[nj];
            else if (EPI == 3) v += bias[nj] + Cin[(size_t)mi * N + nj];
            C[(size_t)mi * N + nj] = v;
        }
    }
}

// ---------------------------- Abar = I + dt*A ------------------------------
__global__ void build_abar_kernel(const float* __restrict__ A)
{
    const int idx = blockIdx.x * 256 + threadIdx.x;   // DEPTH*S*S total
    const int r = (idx >> 7) & 127, c = idx & 127;
    g_Abar[idx] = DT_F * A[idx] + (r == c ? 1.f : 0.f);
}

// ------------------------------ chunked scan -------------------------------
// grid (KC_CHUNKS, B_N), 128 threads; thread s holds Abar row s in registers.
__global__ void __launch_bounds__(128)
scan_chunk_kernel(const float* __restrict__ Ab, const float* __restrict__ ub,
                  const float* __restrict__ carry_in, float* __restrict__ hs,
                  float* __restrict__ lf, int pass)
{
    const int c = blockIdx.x, b = blockIdx.y, s = threadIdx.x;
    __shared__ float h_sh[S_DIM];
    float areg[S_DIM];
#pragma unroll
    for (int k = 0; k < S_DIM; k++) areg[k] = Ab[s * S_DIM + k];
    h_sh[s] = (pass == 2) ? carry_in[(c * B_N + b) * S_DIM + s] : 0.f;
    __syncthreads();

    const float* ubp = ub + ((size_t)b * L_SEQ + c * T_CHUNK) * S_DIM;
    float* hsp = hs + ((size_t)b * L_SEQ + c * T_CHUNK) * S_DIM; // only used pass 2
    float ubv = ubp[s];
#pragma unroll 1
    for (int t = 0; t < T_CHUNK; t++) {
        const float nxt = (t + 1 < T_CHUNK) ? ubp[(t + 1) * S_DIM + s] : 0.f;
        float a0 = 0.f, a1 = 0.f, a2 = 0.f, a3 = 0.f;
#pragma unroll
        for (int k = 0; k < S_DIM; k += 4) {
            a0 = fmaf(areg[k + 0], h_sh[k + 0], a0);
            a1 = fmaf(areg[k + 1], h_sh[k + 1], a1);
            a2 = fmaf(areg[k + 2], h_sh[k + 2], a2);
            a3 = fmaf(areg[k + 3], h_sh[k + 3], a3);
        }
        const float hn = ubv + ((a0 + a1) + (a2 + a3));
        __syncthreads();
        h_sh[s] = hn;
        if (pass == 2) hsp[t * S_DIM + s] = hn;
        __syncthreads();
        ubv = nxt;
    }
    if (pass == 1) lf[(c * B_N + b) * S_DIM + s] = h_sh[s];
}

// sequential combine across chunks: H = Pow @ H + lf[c]; carry_in[c] = H_{c-1}
__global__ void __launch_bounds__(128)
combine_kernel(const float* __restrict__ Pw, const float* __restrict__ lf,
               float* __restrict__ ci)
{
    const int b = blockIdx.x, s = threadIdx.x;
    __shared__ float h_sh[S_DIM];
    float preg[S_DIM];
#pragma unroll
    for (int k = 0; k < S_DIM; k++) preg[k] = Pw[s * S_DIM + k];
    h_sh[s] = 0.f;
    ci[(0 * B_N + b) * S_DIM + s] = 0.f;
    __syncthreads();
#pragma unroll 1
    for (int c = 0; c < KC_CHUNKS; c++) {
        float a0 = 0.f, a1 = 0.f, a2 = 0.f, a3 = 0.f;
#pragma unroll
        for (int k = 0; k < S_DIM; k += 4) {
            a0 = fmaf(preg[k + 0], h_sh[k + 0], a0);
            a1 = fmaf(preg[k + 1], h_sh[k + 1], a1);
            a2 = fmaf(preg[k + 2], h_sh[k + 2], a2);
            a3 = fmaf(preg[k + 3], h_sh[k + 3], a3);
        }
        const float hn = lf[(c * B_N + b) * S_DIM + s] + ((a0 + a1) + (a2 + a3));
        __syncthreads();
        h_sh[s] = hn;
        if (c + 1 < KC_CHUNKS) ci[((c + 1) * B_N + b) * S_DIM + s] = hn;
        __syncthreads();
    }
}

// ------------------------------ launcher -----------------------------------
extern "C" void kernel_launch(void* const* d_in, const int* in_sizes, int n_in,
                              void* d_out, int out_size)
{
    const float* x  = (const float*)d_in[0];
    const float* A  = (const float*)d_in[1];
    const float* Bp = (const float*)d_in[2];
    const float* Cp = (const float*)d_in[3];
    const float* Dp = (const float*)d_in[4];
    const float* Wi = (const float*)d_in[5];
    const float* bi = (const float*)d_in[6];
    const float* Wo = (const float*)d_in[7];
    const float* bo = (const float*)d_in[8];
    const float* ga = (const float*)d_in[9];
    const float* be = (const float*)d_in[10];
    float* out = (float*)d_out;
    (void)in_sizes; (void)n_in; (void)out_size;

    float *seq, *t1, *u, *ub, *hs, *ab, *p0, *p1, *lf, *ci;
    cudaGetSymbolAddress((void**)&seq, g_seq);
    cudaGetSymbolAddress((void**)&t1,  g_t1);
    cudaGetSymbolAddress((void**)&u,   g_u);
    cudaGetSymbolAddress((void**)&ub,  g_ub);
    cudaGetSymbolAddress((void**)&hs,  g_hs);
    cudaGetSymbolAddress((void**)&ab,  g_Abar);
    cudaGetSymbolAddress((void**)&p0,  g_p0);
    cudaGetSymbolAddress((void**)&p1,  g_p1);
    cudaGetSymbolAddress((void**)&lf,  g_lf);
    cudaGetSymbolAddress((void**)&ci,  g_ci);

    const size_t MS = (size_t)S_DIM * S_DIM;   // 16384

    // (b,c,p) -> (b,p,c)
    transpose_kernel<<<dim3(32, 32, B_N), dim3(32, 8)>>>(x, seq);

    // Abar for all layers, then Abar^32 via 5 batched squarings (z = layer)
    build_abar_kernel<<<(DEPTH * S_DIM * S_DIM) / 256, 256>>>(A);
    gemm_kernel<64,64,16,4,4,0,false><<<dim3(2,2,DEPTH),256>>>(ab, ab, p0, 128,128,128, 1.f, 0,0,0,0, MS,MS,MS);
    gemm_kernel<64,64,16,4,4,0,false><<<dim3(2,2,DEPTH),256>>>(p0, p0, p1, 128,128,128, 1.f, 0,0,0,0, MS,MS,MS);
    gemm_kernel<64,64,16,4,4,0,false><<<dim3(2,2,DEPTH),256>>>(p1, p1, p0, 128,128,128, 1.f, 0,0,0,0, MS,MS,MS);
    gemm_kernel<64,64,16,4,4,0,false><<<dim3(2,2,DEPTH),256>>>(p0, p0, p1, 128,128,128, 1.f, 0,0,0,0, MS,MS,MS);
    gemm_kernel<64,64,16,4,4,0,false><<<dim3(2,2,DEPTH),256>>>(p1, p1, p0, 128,128,128, 1.f, 0,0,0,0, MS,MS,MS);
    // p0[layer] = Abar^32

    const int Mrows = B_N * L_SEQ;  // 8192
    for (int i = 0; i < DEPTH; i++) {
        const float* Wi_i = Wi + (size_t)i * D_DIM * D_DIM;
        const float* Wo_i = Wo + (size_t)i * D_DIM * D_DIM;
        const float* Bp_i = Bp + (size_t)i * S_DIM * D_DIM;
        const float* Cp_i = Cp + (size_t)i * D_DIM * S_DIM;

        // n = LN(seq)
        layernorm_kernel<<<Mrows, 256>>>(seq, ga + i * D_DIM, be + i * D_DIM, t1);
        // u = n @ Wi^T + bi
        gemm_kernel<128,128,8,8,8,1,true><<<dim3(D_DIM/128, Mrows/128), 256>>>(
            t1, Wi_i, u, Mrows, D_DIM, D_DIM, 1.f, bi + i * D_DIM, 0, 0, 0, 0,0,0);
        // ub = dt * u @ Bp^T   (B,L,S)
        gemm_kernel<64,64,16,4,4,0,true><<<dim3(S_DIM/64, Mrows/64), 256>>>(
            u, Bp_i, ub, Mrows, S_DIM, D_DIM, DT_F, 0, 0, 0, 0, 0,0,0);
        // chunked scan
        scan_chunk_kernel<<<dim3(KC_CHUNKS, B_N), 128>>>(ab + i * MS, ub, ci, hs, lf, 1);
        combine_kernel<<<B_N, 128>>>(p0 + i * MS, lf, ci);
        scan_chunk_kernel<<<dim3(KC_CHUNKS, B_N), 128>>>(ab + i * MS, ub, ci, hs, lf, 2);
        // y = hs @ Cp^T + u*Dp   (y reuses t1)
        gemm_kernel<128,128,8,8,8,2,true><<<dim3(D_DIM/128, Mrows/128), 256>>>(
            hs, Cp_i, t1, Mrows, D_DIM, S_DIM, 1.f, 0, u, Dp + i * D_DIM, 0, 0,0,0);
        // seq = seq + y @ Wo^T + bo   (in place)
        gemm_kernel<128,128,8,8,8,3,true><<<dim3(D_DIM/128, Mrows/128), 256>>>(
            t1, Wo_i, seq, Mrows, D_DIM, D_DIM, 1.f, bo + i * D_DIM, 0, 0, seq, 0,0,0);
    }

    // (b,p,c) -> (b,c,p)
    transpose_kernel<<<dim3(32, 32, B_N), dim3(32, 8)>>>(seq, out);
}

// round 10
// speedup vs baseline: 1.0009x; 1.0009x over previous
#include <cuda_runtime.h>

// ---------------------------------------------------------------------------
// MambaBlock: seq(B,L,d); per layer: LN -> u = n@Wi^T+bi -> ub = dt*u@Bp^T
// -> chunked linear scan h = Abar h + ub -> y = hs@Cp^T + u*Dp
// -> seq += y@Wo^T + bo.   All fp32.
// ---------------------------------------------------------------------------

#define B_N    8
#define L_SEQ  1024
#define D_DIM  1024
#define S_DIM  128
#define DEPTH  4
#define T_CHUNK 32
#define KC_CHUNKS 32
#define DT_F   0.001f

// ------------------------- device scratch (allowed) ------------------------
__device__ float g_seq[(size_t)B_N * L_SEQ * D_DIM];   // residual stream
__device__ float g_t1 [(size_t)B_N * L_SEQ * D_DIM];   // n (then reused as y)
__device__ float g_u  [(size_t)B_N * L_SEQ * D_DIM];   // u
__device__ float g_ub [(size_t)B_N * L_SEQ * S_DIM];   // ub (b,l,s)
__device__ float g_hs [(size_t)B_N * L_SEQ * S_DIM];   // hs (b,l,s)
__device__ float g_Abar[DEPTH * S_DIM * S_DIM];
__device__ float g_p0  [DEPTH * S_DIM * S_DIM];
__device__ float g_p1  [DEPTH * S_DIM * S_DIM];
__device__ float g_lf  [KC_CHUNKS * B_N * S_DIM];      // local chunk finals
__device__ float g_ci  [KC_CHUNKS * B_N * S_DIM];      // carry-in per chunk

// ------------------------------ transpose ---------------------------------
// out[b][j][i] = in[b][i][j], 1024x1024 per batch.  grid(32,32,8) block(32,8)
__global__ void __launch_bounds__(256)
transpose_kernel(const float* __restrict__ in, float* __restrict__ out)
{
    __shared__ float tile[32][33];
    const int b  = blockIdx.z;
    const int i0 = blockIdx.y * 32, j0 = blockIdx.x * 32;
    const int tx = threadIdx.x, ty = threadIdx.y;
    const float* src = in  + (size_t)b * 1048576;
    float*       dst = out + (size_t)b * 1048576;
#pragma unroll
    for (int r = 0; r < 32; r += 8)
        tile[ty + r][tx] = src[(size_t)(i0 + ty + r) * 1024 + j0 + tx];
    __syncthreads();
#pragma unroll
    for (int r = 0; r < 32; r += 8)
        dst[(size_t)(j0 + ty + r) * 1024 + i0 + tx] = tile[tx][ty + r];
}

// ------------------------------ layernorm ---------------------------------
// one block per row of 1024, 256 threads, 1 float4 each
__global__ void __launch_bounds__(256)
layernorm_kernel(const float* __restrict__ x, const float* __restrict__ gamma,
                 const float* __restrict__ beta, float* __restrict__ out)
{
    const int row = blockIdx.x, tid = threadIdx.x;
    const float4 v = ((const float4*)(x + (size_t)row * 1024))[tid];
    float s  = v.x + v.y + v.z + v.w;
    float ss = v.x*v.x + v.y*v.y + v.z*v.z + v.w*v.w;
#pragma unroll
    for (int o = 16; o; o >>= 1) {
        s  += __shfl_xor_sync(0xffffffffu, s,  o);
        ss += __shfl_xor_sync(0xffffffffu, ss, o);
    }
    __shared__ float sh_s[8], sh_ss[8];
    if ((tid & 31) == 0) { sh_s[tid >> 5] = s; sh_ss[tid >> 5] = ss; }
    __syncthreads();
    if (tid < 32) {
        float a = (tid < 8) ? sh_s[tid]  : 0.f;
        float c = (tid < 8) ? sh_ss[tid] : 0.f;
#pragma unroll
        for (int o = 4; o; o >>= 1) {
            a += __shfl_xor_sync(0xffffffffu, a, o);
            c += __shfl_xor_sync(0xffffffffu, c, o);
        }
        if (tid == 0) { sh_s[0] = a; sh_ss[0] = c; }
    }
    __syncthreads();
    const float mean = sh_s[0] * (1.f / 1024.f);
    const float var  = sh_ss[0] * (1.f / 1024.f) - mean * mean;
    const float rstd = rsqrtf(var + 1e-5f);
    const float4 g = ((const float4*)gamma)[tid];
    const float4 bb = ((const float4*)beta)[tid];
    float4 o;
    o.x = (v.x - mean) * rstd * g.x + bb.x;
    o.y = (v.y - mean) * rstd * g.y + bb.y;
    o.z = (v.z - mean) * rstd * g.z + bb.z;
    o.w = (v.w - mean) * rstd * g.w + bb.w;
    ((float4*)(out + (size_t)row * 1024))[tid] = o;
}

// ------------------------------- GEMM --------------------------------------
// C(MxN) = alpha * A(MxK) @ op(B) (+ epilogue), BT: B is (N,K) -> A@B^T,
// else B is (K,N). EPI: 0 none | 1 +bias[n] | 2 +U[m,n]*Dp[n] | 3 +bias[n]+Cin[m,n]
// 256 threads; BM*BK == BN*BK == 1024 floats (1 float4/thread/tile).
template<int BM,int BN,int BK,int TM,int TN,int EPI,bool BT>
__global__ void __launch_bounds__(256)
gemm_kernel(const float* __restrict__ A, const float* __restrict__ B,
            float* __restrict__ C, int M, int N, int K, float alpha,
            const float* __restrict__ bias, const float* __restrict__ U,
            const float* __restrict__ Dp, const float* __restrict__ Cin,
            size_t sA, size_t sB, size_t sC)
{
    static_assert(BM * BK == 1024 && BN * BK == 1024, "tile load sizing");
    static_assert(BM == BN, "BT loader assumes BM==BN");
    __shared__ float As[BK][BM];
    __shared__ float Bs[BK][BN];
    A += (size_t)blockIdx.z * sA;
    B += (size_t)blockIdx.z * sB;
    C += (size_t)blockIdx.z * sC;

    const int tid = threadIdx.x;
    const int m0 = blockIdx.y * BM;
    const int n0 = blockIdx.x * BN;
    const int tx = tid & 15;
    const int ty = tid >> 4;

    const int af4  = BK / 4;
    const int aRow = tid / af4;            // 0..BM-1
    const int aCol = (tid % af4) * 4;      // 0..BK-4
    const int bf4n  = BN / 4;
    const int bRowN = tid / bf4n;          // 0..BK-1
    const int bColN = (tid % bf4n) * 4;

    const float* aPtr = A + (size_t)(m0 + aRow) * K + aCol;
    const float* bPtr = BT ? (B + (size_t)(n0 + aRow) * K + aCol)
                           : (B + (size_t)bRowN * N + n0 + bColN);
    float4 aReg = *(const float4*)aPtr;
    float4 bReg = *(const float4*)bPtr;

    float acc[TM][TN];
#pragma unroll
    for (int i = 0; i < TM; i++)
#pragma unroll
        for (int j = 0; j < TN; j++) acc[i][j] = 0.f;

    const int KT = K / BK;
    for (int kt = 0; kt < KT; ++kt) {
        __syncthreads();
        As[aCol + 0][aRow] = aReg.x; As[aCol + 1][aRow] = aReg.y;
        As[aCol + 2][aRow] = aReg.z; As[aCol + 3][aRow] = aReg.w;
        if (BT) {
            Bs[aCol + 0][aRow] = bReg.x; Bs[aCol + 1][aRow] = bReg.y;
            Bs[aCol + 2][aRow] = bReg.z; Bs[aCol + 3][aRow] = bReg.w;
        } else {
            *(float4*)&Bs[bRowN][bColN] = bReg;
        }
        __syncthreads();
        if (kt + 1 < KT) {
            aPtr += BK;
            aReg = *(const float4*)aPtr;
            if (BT) bPtr += BK; else bPtr += (size_t)BK * N;
            bReg = *(const float4*)bPtr;
        }
#pragma unroll
        for (int k = 0; k < BK; k++) {
            float ar[TM], br[TN];
            float4 q;
            q = *(const float4*)&As[k][ty * 4];
            ar[0] = q.x; ar[1] = q.y; ar[2] = q.z; ar[3] = q.w;
            if (TM == 8) {
                q = *(const float4*)&As[k][BM / 2 + ty * 4];
                ar[4] = q.x; ar[5] = q.y; ar[6] = q.z; ar[7] = q.w;
            }
            q = *(const float4*)&Bs[k][tx * 4];
            br[0] = q.x; br[1] = q.y; br[2] = q.z; br[3] = q.w;
            if (TN == 8) {
                q = *(const float4*)&Bs[k][BN / 2 + tx * 4];
                br[4] = q.x; br[5] = q.y; br[6] = q.z; br[7] = q.w;
            }
#pragma unroll
            for (int i = 0; i < TM; i++)
#pragma unroll
                for (int j = 0; j < TN; j++)
                    acc[i][j] = fmaf(ar[i], br[j], acc[i][j]);
        }
    }

#pragma unroll
    for (int i = 0; i < TM; i++) {
        const int mi = m0 + ((TM == 8) ? ((i & 3) + ty * 4 + (i >> 2) * (BM / 2))
                                       : (ty * 4 + i));
#pragma unroll
        for (int j = 0; j < TN; j++) {
            const int nj = n0 + ((TN == 8) ? ((j & 3) + tx * 4 + (j >> 2) * (BN / 2))
                                           : (tx * 4 + j));
            float v = alpha * acc[i][j];
            if (EPI == 1)      v += bias[nj];
            else if (EPI == 2) v += U[(size_t)mi * N + nj] * Dp[nj];
            else if (EPI == 3) v += bias[nj] + Cin[(size_t)mi * N + nj];
            C[(size_t)mi * N + nj] = v;
        }
    }
}

// ---------------------------- Abar = I + dt*A ------------------------------
__global__ void build_abar_kernel(const float* __restrict__ A)
{
    const int idx = blockIdx.x * 256 + threadIdx.x;   // DEPTH*S*S total
    const int r = (idx >> 7) & 127, c = idx & 127;
    g_Abar[idx] = DT_F * A[idx] + (r == c ? 1.f : 0.f);
}

// ------------------------------ chunked scan -------------------------------
// grid (KC_CHUNKS, B_N), 128 threads; thread s holds Abar row s in registers.
__global__ void __launch_bounds__(128)
scan_chunk_kernel(const float* __restrict__ Ab, const float* __restrict__ ub,
                  const float* __restrict__ carry_in, float* __restrict__ hs,
                  float* __restrict__ lf, int pass)
{
    const int c = blockIdx.x, b = blockIdx.y, s = threadIdx.x;
    __shared__ float h_sh[S_DIM];
    float areg[S_DIM];
#pragma unroll
    for (int k = 0; k < S_DIM; k++) areg[k] = Ab[s * S_DIM + k];
    h_sh[s] = (pass == 2) ? carry_in[(c * B_N + b) * S_DIM + s] : 0.f;
    __syncthreads();

    const float* ubp = ub + ((size_t)b * L_SEQ + c * T_CHUNK) * S_DIM;
    float* hsp = hs + ((size_t)b * L_SEQ + c * T_CHUNK) * S_DIM; // only used pass 2
    float ubv = ubp[s];
#pragma unroll 1
    for (int t = 0; t < T_CHUNK; t++) {
        const float nxt = (t + 1 < T_CHUNK) ? ubp[(t + 1) * S_DIM + s] : 0.f;
        float a0 = 0.f, a1 = 0.f, a2 = 0.f, a3 = 0.f;
#pragma unroll
        for (int k = 0; k < S_DIM; k += 4) {
            a0 = fmaf(areg[k + 0], h_sh[k + 0], a0);
            a1 = fmaf(areg[k + 1], h_sh[k + 1], a1);
            a2 = fmaf(areg[k + 2], h_sh[k + 2], a2);
            a3 = fmaf(areg[k + 3], h_sh[k + 3], a3);
        }
        const float hn = ubv + ((a0 + a1) + (a2 + a3));
        __syncthreads();
        h_sh[s] = hn;
        if (pass == 2) hsp[t * S_DIM + s] = hn;
        __syncthreads();
        ubv = nxt;
    }
    if (pass == 1) lf[(c * B_N + b) * S_DIM + s] = h_sh[s];
}

// sequential combine across chunks: H = Pow @ H + lf[c]; carry_in[c] = H_{c-1}
__global__ void __launch_bounds__(128)
combine_kernel(const float* __restrict__ Pw, const float* __restrict__ lf,
               float* __restrict__ ci)
{
    const int b = blockIdx.x, s = threadIdx.x;
    __shared__ float h_sh[S_DIM];
    float preg[S_DIM];
#pragma unroll
    for (int k = 0; k < S_DIM; k++) preg[k] = Pw[s * S_DIM + k];
    h_sh[s] = 0.f;
    ci[(0 * B_N + b) * S_DIM + s] = 0.f;
    __syncthreads();
#pragma unroll 1
    for (int c = 0; c < KC_CHUNKS; c++) {
        float a0 = 0.f, a1 = 0.f, a2 = 0.f, a3 = 0.f;
#pragma unroll
        for (int k = 0; k < S_DIM; k += 4) {
            a0 = fmaf(preg[k + 0], h_sh[k + 0], a0);
            a1 = fmaf(preg[k + 1], h_sh[k + 1], a1);
            a2 = fmaf(preg[k + 2], h_sh[k + 2], a2);
            a3 = fmaf(preg[k + 3], h_sh[k + 3], a3);
        }
        const float hn = lf[(c * B_N + b) * S_DIM + s] + ((a0 + a1) + (a2 + a3));
        __syncthreads();
        h_sh[s] = hn;
        if (c + 1 < KC_CHUNKS) ci[((c + 1) * B_N + b) * S_DIM + s] = hn;
        __syncthreads();
    }
}

// ------------------------------ launcher -----------------------------------
extern "C" void kernel_launch(void* const* d_in, const int* in_sizes, int n_in,
                              void* d_out, int out_size)
{
    const float* x  = (const float*)d_in[0];
    const float* A  = (const float*)d_in[1];
    const float* Bp = (const float*)d_in[2];
    const float* Cp = (const float*)d_in[3];
    const float* Dp = (const float*)d_in[4];
    const float* Wi = (const float*)d_in[5];
    const float* bi = (const float*)d_in[6];
    const float* Wo = (const float*)d_in[7];
    const float* bo = (const float*)d_in[8];
    const float* ga = (const float*)d_in[9];
    const float* be = (const float*)d_in[10];
    float* out = (float*)d_out;
    (void)in_sizes; (void)n_in; (void)out_size;

    float *seq, *t1, *u, *ub, *hs, *ab, *p0, *p1, *lf, *ci;
    cudaGetSymbolAddress((void**)&seq, g_seq);
    cudaGetSymbolAddress((void**)&t1,  g_t1);
    cudaGetSymbolAddress((void**)&u,   g_u);
    cudaGetSymbolAddress((void**)&ub,  g_ub);
    cudaGetSymbolAddress((void**)&hs,  g_hs);
    cudaGetSymbolAddress((void**)&ab,  g_Abar);
    cudaGetSymbolAddress((void**)&p0,  g_p0);
    cudaGetSymbolAddress((void**)&p1,  g_p1);
    cudaGetSymbolAddress((void**)&lf,  g_lf);
    cudaGetSymbolAddress((void**)&ci,  g_ci);

    const size_t MS = (size_t)S_DIM * S_DIM;   // 16384

    // (b,c,p) -> (b,p,c)
    transpose_kernel<<<dim3(32, 32, B_N), dim3(32, 8)>>>(x, seq);

    // Abar for all layers, then Abar^32 via 5 batched squarings (z = layer)
    build_abar_kernel<<<(DEPTH * S_DIM * S_DIM) / 256, 256>>>(A);
    gemm_kernel<64,64,16,4,4,0,false><<<dim3(2,2,DEPTH),256>>>(ab, ab, p0, 128,128,128, 1.f, 0,0,0,0, MS,MS,MS);
    gemm_kernel<64,64,16,4,4,0,false><<<dim3(2,2,DEPTH),256>>>(p0, p0, p1, 128,128,128, 1.f, 0,0,0,0, MS,MS,MS);
    gemm_kernel<64,64,16,4,4,0,false><<<dim3(2,2,DEPTH),256>>>(p1, p1, p0, 128,128,128, 1.f, 0,0,0,0, MS,MS,MS);
    gemm_kernel<64,64,16,4,4,0,false><<<dim3(2,2,DEPTH),256>>>(p0, p0, p1, 128,128,128, 1.f, 0,0,0,0, MS,MS,MS);
    gemm_kernel<64,64,16,4,4,0,false><<<dim3(2,2,DEPTH),256>>>(p1, p1, p0, 128,128,128, 1.f, 0,0,0,0, MS,MS,MS);
    // p0[layer] = Abar^32

    const int Mrows = B_N * L_SEQ;  // 8192
    for (int i = 0; i < DEPTH; i++) {
        const float* Wi_i = Wi + (size_t)i * D_DIM * D_DIM;
        const float* Wo_i = Wo + (size_t)i * D_DIM * D_DIM;
        const float* Bp_i = Bp + (size_t)i * S_DIM * D_DIM;
        const float* Cp_i = Cp + (size_t)i * D_DIM * S_DIM;

        // n = LN(seq)
        layernorm_kernel<<<Mrows, 256>>>(seq, ga + i * D_DIM, be + i * D_DIM, t1);
        // u = n @ Wi^T + bi
        gemm_kernel<128,128,8,8,8,1,true><<<dim3(D_DIM/128, Mrows/128), 256>>>(
            t1, Wi_i, u, Mrows, D_DIM, D_DIM, 1.f, bi + i * D_DIM, 0, 0, 0, 0,0,0);
        // ub = dt * u @ Bp^T   (B,L,S)
        gemm_kernel<64,64,16,4,4,0,true><<<dim3(S_DIM/64, Mrows/64), 256>>>(
            u, Bp_i, ub, Mrows, S_DIM, D_DIM, DT_F, 0, 0, 0, 0, 0,0,0);
        // chunked scan
        scan_chunk_kernel<<<dim3(KC_CHUNKS, B_N), 128>>>(ab + i * MS, ub, ci, hs, lf, 1);
        combine_kernel<<<B_N, 128>>>(p0 + i * MS, lf, ci);
        scan_chunk_kernel<<<dim3(KC_CHUNKS, B_N), 128>>>(ab + i * MS, ub, ci, hs, lf, 2);
        // y = hs @ Cp^T + u*Dp   (y reuses t1)
        gemm_kernel<128,128,8,8,8,2,true><<<dim3(D_DIM/128, Mrows/128), 256>>>(
            hs, Cp_i, t1, Mrows, D_DIM, S_DIM, 1.f, 0, u, Dp + i * D_DIM, 0, 0,0,0);
        // seq = seq + y @ Wo^T + bo   (in place)
        gemm_kernel<128,128,8,8,8,3,true><<<dim3(D_DIM/128, Mrows/128), 256>>>(
            t1, Wo_i, seq, Mrows, D_DIM, D_DIM, 1.f, bo + i * D_DIM, 0, 0, seq, 0,0,0);
    }

    // (b,p,c) -> (b,c,p)
    transpose_kernel<<<dim3(32, 32, B_N), dim3(32, 8)>>>(seq, out);
}